// round 4
// baseline (speedup 1.0000x reference)
#include <cuda_runtime.h>
#include <cuda_bf16.h>
#include <math.h>

#define N_NODES 10000
#define N_EDGES 320000
#define MUL 32
#define HH 4

__device__ __align__(16) float g_wkv [N_EDGES * 256];   // per-edge MLP outputs [wk(128)|wv(128)]
__device__ __align__(16) float g_qpre[N_NODES * 1024];  // per-node precomputed query side
__device__ __align__(16) float g_z   [N_NODES * 4];     // attention normalizer per head
__device__ __align__(16) float g_agg [N_NODES * 256];   // unnormalized aggregation

#define INV3F 0.57735026918962576f
#define INVFAN 0.015625f            /* 1/64 */

// ---------------------------------------------------------------- zero scratch
__global__ void ek_zero_kernel() {
    int i = blockIdx.x * blockDim.x + threadIdx.x;
    int stride = gridDim.x * blockDim.x;
    float4 z4 = make_float4(0.f, 0.f, 0.f, 0.f);
    for (int j = i; j < N_NODES * 64; j += stride) ((float4*)g_agg)[j] = z4;
    for (int j = i; j < N_NODES;      j += stride) ((float4*)g_z)[j]   = z4;
}

// ---------------------------------------------------------------- Qpre precompute
// Layout per node: for h in 0..3, 256 floats:
//   [ Q0_h(32 over v) | Q1_h(32) | Q2_h d-major (3x32) | Q3_h d-major (3x32) ]
// Q0[h][v] = invfan * sum_u xs[u] W_dot[0][h][u][v]            (pairs k0)
// Q2[h][d][v] = invfan*inv3 * sum_u xv[u][d] W_dot[2][h][u][v] (pairs kv0)
// W_dot is (4, H, 32, 32) = 16384 floats -> staged in DYNAMIC smem (66 KB).
__global__ void __launch_bounds__(256) ek_qpre_kernel(const float* __restrict__ nodef,
                                                      const float* __restrict__ wdot) {
    extern __shared__ float qsm[];
    float* s_w = qsm;            // 16384 floats
    float* s_x = qsm + 16384;    // 128 floats
    int t = threadIdx.x;
    for (int i = t; i < 16384; i += 256) s_w[i] = wdot[i];
    for (int nn = 0; nn < 10; nn++) {
        int n = blockIdx.x * 10 + nn;
        __syncthreads();
        if (t < 32) *(float4*)&s_x[t * 4] = *(const float4*)(nodef + (size_t)n * 128 + t * 4);
        __syncthreads();
#pragma unroll
        for (int rep = 0; rep < 4; rep++) {
            int o = t + rep * 256;
            int h = o >> 8, i = o & 255;
            float acc = 0.f;
            if (i < 64) {
                int p = (i < 32) ? 0 : 1;
                int v = i & 31;
                const float* W = s_w + (p * 4 + h) * 1024 + v;
#pragma unroll
                for (int u = 0; u < 32; u++) acc += s_x[u] * W[u * 32];
                acc *= INVFAN;
            } else {
                int p  = (i < 160) ? 2 : 3;
                int tt = (i < 160) ? (i - 64) : (i - 160);
                int d = tt >> 5, v = tt & 31;
                const float* W = s_w + (p * 4 + h) * 1024 + v;
#pragma unroll
                for (int u = 0; u < 32; u++) acc += s_x[32 + 3 * u + d] * W[u * 32];
                acc *= INVFAN * INV3F;
            }
            g_qpre[(size_t)n * 1024 + o] = acc;
        }
    }
}

// ---------------------------------------------------------------- fused dual MLP
// 64 edges/block, 256 threads, 8x8 register tiles over (edge, output) of the
// 64->256 layer2 (outputs 0..127 = wk MLP, 128..255 = wv MLP).
__global__ void __launch_bounds__(256) ek_mlp_kernel(const float* __restrict__ xattr,
    const float* __restrict__ wk1, const float* __restrict__ bk1, const float* __restrict__ wk2,
    const float* __restrict__ wv1, const float* __restrict__ bv1, const float* __restrict__ wv2) {
    extern __shared__ float sm[];
    float* s_w2 = sm;            // [64][256]      16384 floats
    float* s_h  = sm + 16384;    // [128][64]       8192 (rows 0..63 = hk, 64..127 = hv)
    float* s_w1 = sm + 24576;    // [8][128]        1024
    float* s_b  = sm + 25600;    // [128]            128
    float* s_x  = sm + 25728;    // [64][9] padded   576
    int t = threadIdx.x;
    int e0 = blockIdx.x * 64;

    for (int i = t; i < 8192; i += 256) {
        int c = i >> 7, j = i & 127;
        s_w2[c * 256 + j]       = wk2[i];
        s_w2[c * 256 + 128 + j] = wv2[i];
    }
    for (int i = t; i < 512; i += 256) {
        int b = i >> 6, c = i & 63;
        s_w1[b * 128 + c]      = wk1[i];
        s_w1[b * 128 + 64 + c] = wv1[i];
    }
    if (t < 64) { s_b[t] = bk1[t]; s_b[64 + t] = bv1[t]; }
    for (int i = t; i < 512; i += 256) s_x[(i >> 3) * 9 + (i & 7)] = xattr[(size_t)e0 * 8 + i];
    __syncthreads();

    const float inv8 = 0.35355339059327373f;  // 1/sqrt(8)
    for (int i = t; i < 8192; i += 256) {
        int e = i & 63, c = i >> 6;           // c 0..127 (hk | hv)
        float acc = 0.f;
#pragma unroll
        for (int b = 0; b < 8; b++) acc += s_x[e * 9 + b] * s_w1[b * 128 + c];
        acc = acc * inv8 + s_b[c];
        // jax.nn.gelu default: tanh approximation
        float u2 = 0.7978845608028654f * (acc + 0.044715f * acc * acc * acc);
        s_h[c * 64 + e] = 0.5f * acc * (1.f + tanhf(u2));
    }
    __syncthreads();

    int eg = t & 7, jg = t >> 3;
    int ebase = eg * 8, jbase = jg * 8;
    const float* hp = s_h + ((jg >= 16) ? 64 * 64 : 0);
    float acc[8][8];
#pragma unroll
    for (int a = 0; a < 8; a++)
#pragma unroll
        for (int b = 0; b < 8; b++) acc[a][b] = 0.f;

#pragma unroll 4
    for (int c = 0; c < 64; c++) {
        float4 ha = *(const float4*)&hp[c * 64 + ebase];
        float4 hb = *(const float4*)&hp[c * 64 + ebase + 4];
        float4 wa = *(const float4*)&s_w2[c * 256 + jbase];
        float4 wb = *(const float4*)&s_w2[c * 256 + jbase + 4];
        float hh[8] = {ha.x, ha.y, ha.z, ha.w, hb.x, hb.y, hb.z, hb.w};
        float ww[8] = {wa.x, wa.y, wa.z, wa.w, wb.x, wb.y, wb.z, wb.w};
#pragma unroll
        for (int a = 0; a < 8; a++)
#pragma unroll
            for (int b = 0; b < 8; b++) acc[a][b] += hh[a] * ww[b];
    }
    const float inv64 = 0.125f;  // 1/sqrt(64)
#pragma unroll
    for (int a = 0; a < 8; a++) {
        size_t base = ((size_t)(e0 + ebase + a)) * 256 + jbase;
        float4 o1 = make_float4(acc[a][0] * inv64, acc[a][1] * inv64, acc[a][2] * inv64, acc[a][3] * inv64);
        float4 o2 = make_float4(acc[a][4] * inv64, acc[a][5] * inv64, acc[a][6] * inv64, acc[a][7] * inv64);
        __stcs((float4*)(g_wkv + base), o1);
        __stcs((float4*)(g_wkv + base + 4), o2);
    }
}

// ---------------------------------------------------------------- edge megakernel
__device__ __forceinline__ float feat_one(int i, const float* row, const float* w,
                                          float ys, float yv0, float yv1, float yv2) {
    if (i < 32) return w[i] * row[i] * ys;                             // k0 / v0
    if (i < 64) {                                                      // k1 / v1
        int u = i - 32;
        float dv = row[32 + 3 * u] * yv0 + row[33 + 3 * u] * yv1 + row[34 + 3 * u] * yv2;
        return w[i] * dv * INV3F;
    }
    if (i < 160) {                                                     // kv0 d-major
        int tt = i - 64; int d = tt >> 5, u = tt & 31;
        float yd = (d == 0) ? yv0 : ((d == 1) ? yv1 : yv2);
        return w[64 + u] * row[u] * yd;
    }
    {                                                                  // kv1 d-major
        int tt = i - 160; int d = tt >> 5, u = tt & 31;
        return w[96 + u] * row[32 + 3 * u + d] * ys;
    }
}

__device__ __forceinline__ int feat_head(int i) {
    if (i < 64) return (i & 31) >> 3;
    int tt = (i < 160) ? (i - 64) : (i - 160);
    return (tt & 31) >> 3;
}

__device__ __forceinline__ void red_v4(float* p, float a, float b, float c, float d) {
    asm volatile("red.global.add.v4.f32 [%0], {%1, %2, %3, %4};"
                 :: "l"(p), "f"(a), "f"(b), "f"(c), "f"(d) : "memory");
}

__global__ void __launch_bounds__(256) ek_edge_kernel(
    const int* __restrict__ esrc, const int* __restrict__ edst,
    const float* __restrict__ eattr, const float* __restrict__ ecut,
    const float* __restrict__ nodef) {
    __shared__ float s_row[8][136];
    __shared__ float s_w[8][256];
    int warp = threadIdx.x >> 5, lane = threadIdx.x & 31;
    int e = blockIdx.x * 8 + warp;
    if (e >= N_EDGES) return;

    int s = esrc[e], dd = edst[e];
    float4 ea = *(const float4*)(eattr + (size_t)e * 4);
    float ys = ea.x, yv0 = ea.y, yv1 = ea.z, yv2 = ea.w;
    float cw = ecut[e];

    *(float4*)&s_row[warp][lane * 4] = *(const float4*)(nodef + (size_t)s * 128 + lane * 4);
    const float4* wv4 = (const float4*)(g_wkv + (size_t)e * 256);
    *(float4*)&s_w[warp][lane * 4]       = __ldcs(wv4 + lane);
    *(float4*)&s_w[warp][128 + lane * 4] = __ldcs(wv4 + 32 + lane);
    __syncwarp();

    const float* row = s_row[warp];
    const float* wk  = s_w[warp];
    int iA = 4 * lane, iB = 128 + 4 * lane;

    float kA[4], kB[4];
#pragma unroll
    for (int j = 0; j < 4; j++) {
        kA[j] = feat_one(iA + j, row, wk, ys, yv0, yv1, yv2);
        kB[j] = feat_one(iB + j, row, wk, ys, yv0, yv1, yv2);
    }

    const float4* q = (const float4*)(g_qpre + (size_t)dd * 1024);
    float dh[4];
#pragma unroll
    for (int h = 0; h < 4; h++) {
        float4 qa = q[h * 64 + lane];
        float4 qb = q[h * 64 + 32 + lane];
        dh[h] = qa.x * kA[0] + qa.y * kA[1] + qa.z * kA[2] + qa.w * kA[3]
              + qb.x * kB[0] + qb.y * kB[1] + qb.z * kB[2] + qb.w * kB[3];
    }
#pragma unroll
    for (int off = 16; off; off >>= 1) {
#pragma unroll
        for (int h = 0; h < 4; h++) dh[h] += __shfl_xor_sync(0xffffffffu, dh[h], off);
    }

    float ew[4], sa[4];
#pragma unroll
    for (int h = 0; h < 4; h++) {
        ew[h] = cw * expf(dh[h]);
        sa[h] = sqrtf(ew[h]);     // sqrt(expw); /sqrt(z) deferred to epilogue
    }
    if (lane == 0) red_v4(g_z + (size_t)dd * 4, ew[0], ew[1], ew[2], ew[3]);

    const float* wv = wk + 128;
    float vA[4], vB[4];
#pragma unroll
    for (int j = 0; j < 4; j++) {
        vA[j] = feat_one(iA + j, row, wv, ys, yv0, yv1, yv2) * sa[feat_head(iA + j)];
        vB[j] = feat_one(iB + j, row, wv, ys, yv0, yv1, yv2) * sa[feat_head(iB + j)];
    }
    red_v4(g_agg + (size_t)dd * 256 + iA, vA[0], vA[1], vA[2], vA[3]);
    red_v4(g_agg + (size_t)dd * 256 + iB, vB[0], vB[1], vB[2], vB[3]);
}

// ---------------------------------------------------------------- node epilogue
__global__ void __launch_bounds__(128) ek_out_kernel(const float* __restrict__ wls,
                                                     const float* __restrict__ wlv,
                                                     float* __restrict__ out) {
    __shared__ float s_ws[2048];
    __shared__ float s_wv[2048];
    __shared__ float s_s[64];
    __shared__ float s_v[192];   // [d][u]
    __shared__ float s_sc[4];
    int t = threadIdx.x;
    for (int i = t; i < 2048; i += 128) { s_ws[i] = wls[i]; s_wv[i] = wlv[i]; }
    const float inv_l = 0.125f;  // 1/sqrt(64)

    for (int nn = 0; nn < 10; nn++) {
        int n = blockIdx.x * 10 + nn;
        __syncthreads();
        if (t < 4) {
            float zz = g_z[(size_t)n * 4 + t];
            s_sc[t] = (zz == 0.f) ? 1.f : (1.0f / sqrtf(zz));
        }
        __syncthreads();
        for (int i = t; i < 256; i += 128) {
            float val = g_agg[(size_t)n * 256 + i];
            if (i < 64) {
                s_s[i] = val * s_sc[(i & 31) >> 3];
            } else {
                int f = i - 64;
                int blk = (f < 96) ? 0 : 1;
                int r = f - blk * 96;
                int d = r >> 5, uu = r & 31;
                s_v[d * 64 + blk * 32 + uu] = val * s_sc[uu >> 3];
            }
        }
        __syncthreads();
        if (t < 32) {
            int w = t;
            float acc = 0.f;
#pragma unroll
            for (int u = 0; u < 64; u++) acc += s_s[u] * s_ws[u * 32 + w];
            out[(size_t)n * 128 + w] = acc * inv_l;
        } else {
            int o = t - 32;
            int d = o >> 5, w = o & 31;
            float acc = 0.f;
#pragma unroll
            for (int u = 0; u < 64; u++) acc += s_v[d * 64 + u] * s_wv[u * 32 + w];
            out[(size_t)n * 128 + 32 + w * 3 + d] = acc * inv_l;
        }
    }
}

// ---------------------------------------------------------------- launch
extern "C" void kernel_launch(void* const* d_in, const int* in_sizes, int n_in,
                              void* d_out, int out_size) {
    const int*   esrc  = (const int*)d_in[0];
    const int*   edst  = (const int*)d_in[1];
    const float* xattr = (const float*)d_in[2];
    const float* eattr = (const float*)d_in[3];
    const float* ecut  = (const float*)d_in[4];
    const float* nodef = (const float*)d_in[5];
    const float* wk1   = (const float*)d_in[6];
    const float* bk1   = (const float*)d_in[7];
    const float* wk2   = (const float*)d_in[8];
    const float* wv1   = (const float*)d_in[9];
    const float* bv1   = (const float*)d_in[10];
    const float* wv2   = (const float*)d_in[11];
    const float* wdot  = (const float*)d_in[12];
    const float* wls   = (const float*)d_in[13];
    const float* wlv   = (const float*)d_in[14];
    float* out = (float*)d_out;

    const int mlp_smem  = 26304 * 4;  // 105,216 B dynamic smem
    const int qpre_smem = 16512 * 4;  //  66,048 B dynamic smem (full W_dot + node row)
    cudaFuncSetAttribute(ek_mlp_kernel,  cudaFuncAttributeMaxDynamicSharedMemorySize, mlp_smem);
    cudaFuncSetAttribute(ek_qpre_kernel, cudaFuncAttributeMaxDynamicSharedMemorySize, qpre_smem);

    ek_zero_kernel<<<1024, 256>>>();
    ek_qpre_kernel<<<N_NODES / 10, 256, qpre_smem>>>(nodef, wdot);
    ek_mlp_kernel<<<N_EDGES / 64, 256, mlp_smem>>>(xattr, wk1, bk1, wk2, wv1, bv1, wv2);
    ek_edge_kernel<<<N_EDGES / 8, 256>>>(esrc, edst, eattr, ecut, nodef);
    ek_out_kernel<<<N_NODES / 10, 128>>>(wls, wlv, out);
}